// round 1
// baseline (speedup 1.0000x reference)
#include <cuda_runtime.h>
#include <cuda_bf16.h>
#include <math.h>

#define B 32
#define T 64
#define N 128
#define D 64
#define K2 129            // 2D+1
#define KD (K2*D)         // 8256
#define HSZ (B*N*D)       // 262144
#define GRID 128
#define BLOCK 256
#define SMEM_BYTES (110*1024)

// ---------------- device scratch (static; no runtime allocation) ----------------
__device__ float g_vv[N*5];
__device__ float g_Weff[3*N*KD];     // [gate r/u/c][n][k][d]
__device__ float g_beff[3*N*D];
__device__ float g_invtot[B*N];
__device__ float g_hbuf[2*HSZ];
__device__ float g_comb[B*N*K2];

// ---------------- grid barrier ----------------
__device__ unsigned int g_bar_cnt = 0;
__device__ volatile unsigned int g_bar_gen = 0;

__device__ __forceinline__ void grid_barrier() {
    __syncthreads();
    if (threadIdx.x == 0) {
        __threadfence();
        unsigned int gen = g_bar_gen;
        if (atomicAdd(&g_bar_cnt, 1u) == GRID - 1u) {
            g_bar_cnt = 0;
            __threadfence();
            g_bar_gen = gen + 1u;
        } else {
            while (g_bar_gen == gen) { }
            __threadfence();
        }
    }
    __syncthreads();
}

__device__ __forceinline__ float sigmoidf_(float x) {
    return 1.0f / (1.0f + __expf(-x));
}

__global__ void __launch_bounds__(BLOCK, 1)
cgrnn_persistent(const float* __restrict__ obs,      // [B,T,N,D]
                 const float* __restrict__ mask,     // [B,T,N]
                 const int*   __restrict__ lengths,  // [B]
                 const float* __restrict__ avg,      // [B,T,N]
                 const float* __restrict__ vpe,      // [N,768]
                 const float* __restrict__ rarW,     // [N,N]
                 const float* __restrict__ adjI,     // [N,N]
                 const float* __restrict__ W1,       // [768,128]
                 const float* __restrict__ b1,       // [128]
                 const float* __restrict__ W2,       // [128,5]
                 const float* __restrict__ b2,       // [5]
                 const float* __restrict__ Wr, const float* __restrict__ brp,
                 const float* __restrict__ Wu, const float* __restrict__ bup,
                 const float* __restrict__ Wc, const float* __restrict__ bcp,
                 float* __restrict__ out)            // [B,N,D]
{
    extern __shared__ char smem_raw[];
    const int tid = threadIdx.x;
    const int bid = blockIdx.x;

    // ========== P1: hypernetwork vv[n,e] (one block per node) ==========
    {
        float* hid = (float*)smem_raw;   // [128]
        int n = bid;
        if (tid < 128) {
            float acc = b1[tid];
            for (int k = 0; k < 768; k++)
                acc = fmaf(vpe[n*768 + k], W1[k*128 + tid], acc);
            hid[tid] = fmaxf(acc, 0.0f);
        }
        __syncthreads();
        if (tid < 5) {
            float acc = b2[tid];
            for (int d = 0; d < 128; d++)
                acc = fmaf(hid[d], W2[d*5 + tid], acc);
            g_vv[n*5 + tid] = acc;
        }
    }
    grid_barrier();

    // ========== P2: effective weights, biases, inv_tot, zero h0 ==========
    {
        const float* Wsrc0 = Wr; const float* Wsrc1 = Wu; const float* Wsrc2 = Wc;
        const int total = 3 * N * KD;
        for (int idx = bid*BLOCK + tid; idx < total; idx += GRID*BLOCK) {
            int g = idx / (N*KD);
            int rem = idx - g*(N*KD);
            int n = rem / KD;
            int kd = rem - n*KD;
            const float* src = (g == 0) ? Wsrc0 : (g == 1) ? Wsrc1 : Wsrc2;
            const float* v = &g_vv[n*5];
            float acc = 0.0f;
            #pragma unroll
            for (int e = 0; e < 5; e++) acc = fmaf(v[e], src[e*KD + kd], acc);
            g_Weff[idx] = acc;
        }
        for (int idx = bid*BLOCK + tid; idx < 3*N*D; idx += GRID*BLOCK) {
            int g = idx / (N*D);
            int rem = idx - g*(N*D);
            int n = rem >> 6;
            int d = rem & 63;
            const float* src = (g == 0) ? brp : (g == 1) ? bup : bcp;
            float acc = 0.0f;
            #pragma unroll
            for (int e = 0; e < 5; e++) acc = fmaf(g_vv[n*5 + e], src[e*D + d], acc);
            g_beff[idx] = acc;
        }
        for (int idx = bid*BLOCK + tid; idx < B*N; idx += GRID*BLOCK) {
            int b = idx >> 7;
            int n = idx & 127;
            float s = 0.0f;
            for (int t = 0; t < T; t++) s += mask[(b*T + t)*N + n];
            g_invtot[idx] = 1.0f / (s + 1.0f);
        }
        for (int idx = bid*BLOCK + tid; idx < HSZ; idx += GRID*BLOCK)
            g_hbuf[idx] = 0.0f;
    }
    grid_barrier();

    // ========== time loop ==========
    for (int t = 0; t < T; t++) {
        const float* hprev = g_hbuf + (t & 1) * HSZ;
        float*       hnext = g_hbuf + ((t + 1) & 1) * HSZ;

        // ---- Phase A: comb[b,i,:] for observed i  (block = (b, 32-node chunk)) ----
        {
            const int b  = bid >> 2;
            const int i0 = (bid & 3) * 32;
            float* feat = (float*)smem_raw;          // [128][132] padded
            float* w    = feat + 128*132;            // [<=32][128]
            float* rsv  = w + 32*128;                // [128]
            float* mv   = rsv + 128;                 // [128]
            int*   list = (int*)(mv + 128);          // [32]
            int*   pnob = list + 32;

            if (tid < 128) {
                int j = tid;
                mv[j]  = mask[(b*T + t)*N + j];
                rsv[j] = 0.5f * tanhf(avg[(b*T + t)*N + j] * g_invtot[b*N + j]);
            }
            __syncthreads();
            if (tid < 32) {
                int i = i0 + tid;
                bool ob = (mv[i] != 0.0f);
                unsigned msk = __ballot_sync(0xffffffffu, ob);
                if (ob) list[__popc(msk & ((1u << tid) - 1u))] = i;
                if (tid == 0) *pnob = __popc(msk);
            }
            for (int idx = tid; idx < 128*132; idx += BLOCK) {
                int j = idx / 132;
                int f = idx - j*132;
                float v;
                if (f < 64)        v = obs[((b*T + t)*N + j)*D + f];
                else if (f == 64)  v = rsv[j];
                else if (f < 129)  v = hprev[(b*N + j)*D + (f - 65)];
                else               v = 0.0f;
                feat[idx] = v;
            }
            __syncthreads();
            const int nobs = *pnob;
            for (int idx = tid; idx < nobs*128; idx += BLOCK) {
                int r = idx >> 7;
                int j = idx & 127;
                int i = list[r];
                float wv;
                if (j == i) wv = 1.0f;
                else wv = adjI[i*N + j] *
                          (1.0f - rarW[i*N + j] * fabsf(rsv[i] - rsv[j])) * mv[j];
                w[idx] = wv;
            }
            __syncthreads();
            // 33 float4-groups cover f = 0..131 (cols 129..131 are zero pad)
            for (int wi = tid; wi < nobs*33; wi += BLOCK) {
                int r  = wi / 33;
                int g4 = wi - r*33;
                int i  = list[r];
                const float* wr = &w[r*128];
                const float* fb = feat + g4*4;
                float4 acc = make_float4(0.f, 0.f, 0.f, 0.f);
                #pragma unroll 4
                for (int j = 0; j < 128; j++) {
                    float wj = wr[j];
                    float4 fv = *(const float4*)(fb + j*132);
                    acc.x = fmaf(wj, fv.x, acc.x);
                    acc.y = fmaf(wj, fv.y, acc.y);
                    acc.z = fmaf(wj, fv.z, acc.z);
                    acc.w = fmaf(wj, fv.w, acc.w);
                }
                float* cw = &g_comb[(b*N + i)*K2 + g4*4];
                if (g4 < 32) { cw[0] = acc.x; cw[1] = acc.y; cw[2] = acc.z; cw[3] = acc.w; }
                else         { cw[0] = acc.x; }
            }
        }
        grid_barrier();

        // ---- Phase B: gates + state update  (block = node n, all 32 batches) ----
        {
            const int n = bid;
            float* Wst0   = (float*)smem_raw;        // [129*64]
            float* Wst1   = Wst0 + KD;               // [129*64]
            float* comb_s = Wst1 + KD;               // [32*129]
            float* x_s    = comb_s + B*K2;           // [32*65]
            float* h_s    = x_s + B*65;              // [32*64]
            float* h1_s   = h_s + B*D;               // [32*64]
            float* m_s    = h1_s + B*D;              // [32]
            int*   len_s  = (int*)(m_s + B);         // [32]

            for (int idx = tid; idx < B*K2; idx += BLOCK) {
                int b = idx / K2;
                int k = idx - b*K2;
                comb_s[idx] = g_comb[(b*N + n)*K2 + k];
            }
            for (int idx = tid; idx < B*D; idx += BLOCK) {
                int b = idx >> 6;
                int d = idx & 63;
                x_s[b*65 + d] = obs[((b*T + t)*N + n)*D + d];
                h_s[idx]      = hprev[(b*N + n)*D + d];
            }
            if (tid < B) {
                int b = tid;
                m_s[b] = mask[(b*T + t)*N + n];
                x_s[b*65 + 64] = 0.5f * tanhf(avg[(b*T + t)*N + n] * g_invtot[b*N + n]);
                len_s[b] = lengths[b];
            }
            {
                const float4* s0 = (const float4*)&g_Weff[(0*N + n)*KD];
                const float4* s1 = (const float4*)&g_Weff[(1*N + n)*KD];
                float4* d0 = (float4*)Wst0;
                float4* d1 = (float4*)Wst1;
                for (int idx = tid; idx < KD/4; idx += BLOCK) { d0[idx] = s0[idx]; d1[idx] = s1[idx]; }
            }
            __syncthreads();

            const int b   = tid >> 3;
            const int d0i = (tid & 7) * 8;
            const bool ob = (m_s[b] != 0.0f);
            float h1v[8], uv[8];

            if (ob) {
                float accr[8], accu[8];
                const float* brn = &g_beff[(0*N + n)*D + d0i];
                const float* bun = &g_beff[(1*N + n)*D + d0i];
                #pragma unroll
                for (int j = 0; j < 8; j++) { accr[j] = brn[j]; accu[j] = bun[j]; }
                const float* cb = &comb_s[b*K2];
                for (int k = 0; k < K2; k++) {
                    float c = cb[k];
                    float4 a0 = *(const float4*)&Wst0[k*D + d0i];
                    float4 a1 = *(const float4*)&Wst0[k*D + d0i + 4];
                    float4 u0 = *(const float4*)&Wst1[k*D + d0i];
                    float4 u1 = *(const float4*)&Wst1[k*D + d0i + 4];
                    accr[0] = fmaf(c, a0.x, accr[0]); accr[1] = fmaf(c, a0.y, accr[1]);
                    accr[2] = fmaf(c, a0.z, accr[2]); accr[3] = fmaf(c, a0.w, accr[3]);
                    accr[4] = fmaf(c, a1.x, accr[4]); accr[5] = fmaf(c, a1.y, accr[5]);
                    accr[6] = fmaf(c, a1.z, accr[6]); accr[7] = fmaf(c, a1.w, accr[7]);
                    accu[0] = fmaf(c, u0.x, accu[0]); accu[1] = fmaf(c, u0.y, accu[1]);
                    accu[2] = fmaf(c, u0.z, accu[2]); accu[3] = fmaf(c, u0.w, accu[3]);
                    accu[4] = fmaf(c, u1.x, accu[4]); accu[5] = fmaf(c, u1.y, accu[5]);
                    accu[6] = fmaf(c, u1.z, accu[6]); accu[7] = fmaf(c, u1.w, accu[7]);
                }
                #pragma unroll
                for (int j = 0; j < 8; j++) {
                    float r = sigmoidf_(accr[j]);
                    h1v[j] = r * h_s[b*D + d0i + j];
                    uv[j]  = sigmoidf_(accu[j]);
                    h1_s[b*D + d0i + j] = h1v[j];
                }
            }
            __syncthreads();
            {
                const float4* s2 = (const float4*)&g_Weff[(2*N + n)*KD];
                float4* d0 = (float4*)Wst0;
                for (int idx = tid; idx < KD/4; idx += BLOCK) d0[idx] = s2[idx];
            }
            __syncthreads();

            float h2[8];
            if (ob) {
                float accc[8];
                const float* bcn = &g_beff[(2*N + n)*D + d0i];
                #pragma unroll
                for (int j = 0; j < 8; j++) accc[j] = bcn[j];
                const float* xs = &x_s[b*65];
                for (int k = 0; k < 65; k++) {
                    float z = xs[k];
                    float4 a0 = *(const float4*)&Wst0[k*D + d0i];
                    float4 a1 = *(const float4*)&Wst0[k*D + d0i + 4];
                    accc[0] = fmaf(z, a0.x, accc[0]); accc[1] = fmaf(z, a0.y, accc[1]);
                    accc[2] = fmaf(z, a0.z, accc[2]); accc[3] = fmaf(z, a0.w, accc[3]);
                    accc[4] = fmaf(z, a1.x, accc[4]); accc[5] = fmaf(z, a1.y, accc[5]);
                    accc[6] = fmaf(z, a1.z, accc[6]); accc[7] = fmaf(z, a1.w, accc[7]);
                }
                const float* h1b = &h1_s[b*D];
                for (int k = 0; k < 64; k++) {
                    float z = h1b[k];
                    float4 a0 = *(const float4*)&Wst0[(65 + k)*D + d0i];
                    float4 a1 = *(const float4*)&Wst0[(65 + k)*D + d0i + 4];
                    accc[0] = fmaf(z, a0.x, accc[0]); accc[1] = fmaf(z, a0.y, accc[1]);
                    accc[2] = fmaf(z, a0.z, accc[2]); accc[3] = fmaf(z, a0.w, accc[3]);
                    accc[4] = fmaf(z, a1.x, accc[4]); accc[5] = fmaf(z, a1.y, accc[5]);
                    accc[6] = fmaf(z, a1.z, accc[6]); accc[7] = fmaf(z, a1.w, accc[7]);
                }
                #pragma unroll
                for (int j = 0; j < 8; j++) {
                    float cd = tanhf(accc[j]);
                    h2[j] = h1v[j] + uv[j] * (cd - h1v[j]);
                }
            } else {
                #pragma unroll
                for (int j = 0; j < 8; j++) h2[j] = h_s[b*D + d0i + j];
            }

            float* hn = &hnext[(b*N + n)*D + d0i];
            *(float4*)hn       = make_float4(h2[0], h2[1], h2[2], h2[3]);
            *(float4*)(hn + 4) = make_float4(h2[4], h2[5], h2[6], h2[7]);
            if (t == len_s[b] - 1) {
                float* op = &out[(b*N + n)*D + d0i];
                *(float4*)op       = make_float4(h2[0], h2[1], h2[2], h2[3]);
                *(float4*)(op + 4) = make_float4(h2[4], h2[5], h2[6], h2[7]);
            }
        }
        grid_barrier();
    }
}

extern "C" void kernel_launch(void* const* d_in, const int* in_sizes, int n_in,
                              void* d_out, int out_size) {
    const float* obs     = (const float*)d_in[0];
    const float* mask    = (const float*)d_in[2];
    const int*   lengths = (const int*)d_in[5];
    const float* avg     = (const float*)d_in[6];
    const float* vpe     = (const float*)d_in[7];
    const float* rarW    = (const float*)d_in[8];
    const float* adjI    = (const float*)d_in[9];
    const float* W1      = (const float*)d_in[10];
    const float* b1      = (const float*)d_in[11];
    const float* W2      = (const float*)d_in[12];
    const float* b2      = (const float*)d_in[13];
    const float* Wu      = (const float*)d_in[14];
    const float* bu      = (const float*)d_in[15];
    const float* Wr      = (const float*)d_in[16];
    const float* br      = (const float*)d_in[17];
    const float* Wc      = (const float*)d_in[18];
    const float* bc      = (const float*)d_in[19];
    float* out = (float*)d_out;

    cudaFuncSetAttribute(cgrnn_persistent,
                         cudaFuncAttributeMaxDynamicSharedMemorySize, SMEM_BYTES);
    cgrnn_persistent<<<GRID, BLOCK, SMEM_BYTES>>>(
        obs, mask, lengths, avg, vpe, rarW, adjI,
        W1, b1, W2, b2, Wr, br, Wu, bu, Wc, bc, out);
}

// round 2
// speedup vs baseline: 1.6138x; 1.6138x over previous
#include <cuda_runtime.h>
#include <cuda_bf16.h>
#include <math.h>

#define B_ 32
#define T_ 64
#define N_ 128
#define D_ 64
#define K2 129            // 2D+1
#define KD (K2*D_)        // 8256
#define HSZ (B_*N_*D_)    // 262144
#define GRID 128
#define BLOCK 512
#define SMEM_BYTES (118*1024)

// ---------------- device scratch (static; no runtime allocation) ----------------
__device__ float g_vv[N_*5];
__device__ float g_Weff[3*N_*KD];     // [gate r/u/c][n][k][d]
__device__ float g_beff[3*N_*D_];
__device__ float g_invtot[B_*N_];
__device__ float g_hbuf[2*HSZ];
__device__ float g_comb[B_*N_*K2];

// ---------------- grid barrier ----------------
__device__ unsigned int g_bar_cnt = 0;
__device__ volatile unsigned int g_bar_gen = 0;

__device__ __forceinline__ void grid_barrier() {
    __syncthreads();
    if (threadIdx.x == 0) {
        __threadfence();
        unsigned int gen = g_bar_gen;
        if (atomicAdd(&g_bar_cnt, 1u) == GRID - 1u) {
            g_bar_cnt = 0;
            __threadfence();
            g_bar_gen = gen + 1u;
        } else {
            while (g_bar_gen == gen) { }
            __threadfence();
        }
    }
    __syncthreads();
}

__device__ __forceinline__ float sigmoidf_(float x) {
    return 1.0f / (1.0f + __expf(-x));
}

__global__ void __launch_bounds__(BLOCK, 1)
cgrnn_persistent(const float* __restrict__ obs,      // [B,T,N,D]
                 const float* __restrict__ mask,     // [B,T,N]
                 const int*   __restrict__ lengths,  // [B]
                 const float* __restrict__ avg,      // [B,T,N]
                 const float* __restrict__ vpe,      // [N,768]
                 const float* __restrict__ rarW,     // [N,N]
                 const float* __restrict__ adjI,     // [N,N]
                 const float* __restrict__ W1,       // [768,128]
                 const float* __restrict__ b1,       // [128]
                 const float* __restrict__ W2,       // [128,5]
                 const float* __restrict__ b2,       // [5]
                 const float* __restrict__ Wr, const float* __restrict__ brp,
                 const float* __restrict__ Wu, const float* __restrict__ bup,
                 const float* __restrict__ Wc, const float* __restrict__ bcp,
                 float* __restrict__ out)            // [B,N,D]
{
    extern __shared__ char smem_raw[];
    float* smemf = (float*)smem_raw;
    const int tid = threadIdx.x;
    const int bid = blockIdx.x;

    // ========== P1: hypernetwork vv[n,e] (one block per node) ==========
    {
        int n = bid;
        int q   = tid >> 7;      // 0..3 k-quarter
        int col = tid & 127;
        float acc = 0.0f;
        int k0 = q * 192;
        #pragma unroll 4
        for (int k = k0; k < k0 + 192; k++)
            acc = fmaf(vpe[n*768 + k], W1[k*128 + col], acc);
        smemf[q*128 + col] = acc;
        __syncthreads();
        if (tid < 128) {
            float h = smemf[tid] + smemf[128+tid] + smemf[256+tid] + smemf[384+tid] + b1[tid];
            smemf[512 + tid] = fmaxf(h, 0.0f);
        }
        __syncthreads();
        if (tid < 5) {
            float a = b2[tid];
            for (int d = 0; d < 128; d++)
                a = fmaf(smemf[512 + d], W2[d*5 + tid], a);
            g_vv[n*5 + tid] = a;
        }
    }
    grid_barrier();

    // ========== P2: effective weights, biases, inv_tot, zero h0 ==========
    {
        const int total = 3 * N_ * KD;
        for (int idx = bid*BLOCK + tid; idx < total; idx += GRID*BLOCK) {
            int g = idx / (N_*KD);
            int rem = idx - g*(N_*KD);
            int n = rem / KD;
            int kd = rem - n*KD;
            const float* src = (g == 0) ? Wr : (g == 1) ? Wu : Wc;
            const float* v = &g_vv[n*5];
            float acc = 0.0f;
            #pragma unroll
            for (int e = 0; e < 5; e++) acc = fmaf(v[e], src[e*KD + kd], acc);
            g_Weff[idx] = acc;
        }
        for (int idx = bid*BLOCK + tid; idx < 3*N_*D_; idx += GRID*BLOCK) {
            int g = idx / (N_*D_);
            int rem = idx - g*(N_*D_);
            int n = rem >> 6;
            int d = rem & 63;
            const float* src = (g == 0) ? brp : (g == 1) ? bup : bcp;
            float acc = 0.0f;
            #pragma unroll
            for (int e = 0; e < 5; e++) acc = fmaf(g_vv[n*5 + e], src[e*D_ + d], acc);
            g_beff[idx] = acc;
        }
        for (int idx = bid*BLOCK + tid; idx < B_*N_; idx += GRID*BLOCK) {
            int b = idx >> 7;
            int n = idx & 127;
            float s = 0.0f;
            for (int t = 0; t < T_; t++) s += mask[(b*T_ + t)*N_ + n];
            g_invtot[idx] = 1.0f / (s + 1.0f);
        }
        for (int idx = bid*BLOCK + tid; idx < HSZ; idx += GRID*BLOCK)
            g_hbuf[idx] = 0.0f;
    }
    grid_barrier();

    // ========== time loop ==========
    for (int t = 0; t < T_; t++) {
        const float* hprev = g_hbuf + (t & 1) * HSZ;
        float*       hnext = g_hbuf + ((t + 1) & 1) * HSZ;

        // ---- Phase A: comb[b,i,:] for observed i (block = (b, 32-row chunk)) ----
        {
            const int b  = bid >> 2;
            const int i0 = (bid & 3) * 32;
            float* feat = smemf;                 // [128][132]
            float* wT   = feat + 128*132;        // [128][32]  (transposed, compacted rows)
            float* rsv  = wT + 128*32;           // [128]
            float* mv   = rsv + 128;             // [128]
            int*   list = (int*)(mv + 128);      // [32]
            int*   pnob = list + 32;

            if (tid < 128) {
                int j = tid;
                mv[j]  = mask[(b*T_ + t)*N_ + j];
                rsv[j] = 0.5f * tanhf(avg[(b*T_ + t)*N_ + j] * g_invtot[b*N_ + j]);
            }
            __syncthreads();
            if (tid < 32) {
                int i = i0 + tid;
                bool ob = (mv[i] != 0.0f);
                unsigned msk = __ballot_sync(0xffffffffu, ob);
                if (ob) list[__popc(msk & ((1u << tid) - 1u))] = i;
                if (tid == 0) *pnob = __popc(msk);
            }
            for (int idx = tid; idx < 128*132; idx += BLOCK) {
                int j = idx / 132;
                int f = idx - j*132;
                float v;
                if (f < 64)        v = obs[((b*T_ + t)*N_ + j)*D_ + f];
                else if (f == 64)  v = rsv[j];
                else if (f < 129)  v = hprev[(b*N_ + j)*D_ + (f - 65)];
                else               v = 0.0f;
                feat[idx] = v;
            }
            __syncthreads();
            const int nobs = *pnob;
            // wT[j][ic] for compacted observed rows (zero-padded to 32)
            for (int idx = tid; idx < 128*32; idx += BLOCK) {
                int j  = idx & 127;
                int ic = idx >> 7;
                float wv = 0.0f;
                if (ic < nobs) {
                    int i = list[ic];
                    if (j == i) wv = 1.0f;
                    else wv = adjI[i*N_ + j] *
                              (1.0f - rarW[i*N_ + j] * fabsf(rsv[i] - rsv[j])) * mv[j];
                }
                wT[j*32 + ic] = wv;
            }
            __syncthreads();

            const int RG = (nobs + 3) >> 2;
            for (int tt = tid; tt < RG*33; tt += BLOCK) {
                int rg = tt / 33;
                int fg = tt - rg*33;
                const float* wp = wT + rg*4;
                const float* fp = feat + fg*4;
                float4 a0 = make_float4(0,0,0,0), a1 = a0, a2 = a0, a3 = a0;
                #pragma unroll 4
                for (int j = 0; j < 128; j++) {
                    float4 w4 = *(const float4*)(wp + j*32);
                    float4 f4 = *(const float4*)(fp + j*132);
                    a0.x = fmaf(w4.x, f4.x, a0.x); a0.y = fmaf(w4.x, f4.y, a0.y);
                    a0.z = fmaf(w4.x, f4.z, a0.z); a0.w = fmaf(w4.x, f4.w, a0.w);
                    a1.x = fmaf(w4.y, f4.x, a1.x); a1.y = fmaf(w4.y, f4.y, a1.y);
                    a1.z = fmaf(w4.y, f4.z, a1.z); a1.w = fmaf(w4.y, f4.w, a1.w);
                    a2.x = fmaf(w4.z, f4.x, a2.x); a2.y = fmaf(w4.z, f4.y, a2.y);
                    a2.z = fmaf(w4.z, f4.z, a2.z); a2.w = fmaf(w4.z, f4.w, a2.w);
                    a3.x = fmaf(w4.w, f4.x, a3.x); a3.y = fmaf(w4.w, f4.y, a3.y);
                    a3.z = fmaf(w4.w, f4.z, a3.z); a3.w = fmaf(w4.w, f4.w, a3.w);
                }
                float4 accs[4] = {a0, a1, a2, a3};
                #pragma unroll
                for (int r = 0; r < 4; r++) {
                    int ic = rg*4 + r;
                    if (ic < nobs) {
                        int i = list[ic];
                        float* cw = &g_comb[(b*N_ + i)*K2 + fg*4];
                        if (fg < 32) {
                            cw[0] = accs[r].x; cw[1] = accs[r].y;
                            cw[2] = accs[r].z; cw[3] = accs[r].w;
                        } else {
                            cw[0] = accs[r].x;
                        }
                    }
                }
            }
        }
        grid_barrier();

        // ---- Phase B: gates + state update (block = node n) ----
        {
            const int n = bid;
            float* Wst   = smemf;              // [2*KD] weight stage
            float* combs = Wst + 2*KD;         // [32][129]
            float* zcs   = combs + 32*K2;      // [32][129] : x(65) | h1(64)
            float* hs    = zcs + 32*K2;        // [32][64]
            float* us    = hs + 32*64;         // [32][64]
            float* ms    = us + 32*64;         // [32]
            int*   listB = (int*)(ms + 32);    // [32]
            int*   lenS  = listB + 32;         // [32]
            int*   pnB   = lenS + 32;

            for (int idx = tid; idx < B_*K2; idx += BLOCK) {
                int b = idx / K2;
                int k = idx - b*K2;
                combs[idx] = g_comb[(b*N_ + n)*K2 + k];
            }
            for (int idx = tid; idx < B_*D_; idx += BLOCK) {
                int b = idx >> 6, d = idx & 63;
                zcs[b*K2 + d] = obs[((b*T_ + t)*N_ + n)*D_ + d];
                hs[idx]       = hprev[(b*N_ + n)*D_ + d];
            }
            if (tid < 32) {
                int b = tid;
                float m = mask[(b*T_ + t)*N_ + n];
                ms[b] = m;
                zcs[b*K2 + 64] = 0.5f * tanhf(avg[(b*T_ + t)*N_ + n] * g_invtot[b*N_ + n]);
                lenS[b] = lengths[b];
                bool ob = (m != 0.0f);
                unsigned msk = __ballot_sync(0xffffffffu, ob);
                if (ob) listB[__popc(msk & ((1u << tid) - 1u))] = b;
                if (tid == 0) *pnB = __popc(msk);
            }
            // stage Wr, Wu
            {
                const float4* sr = (const float4*)(g_Weff + (size_t)(0*N_ + n)*KD);
                const float4* su = (const float4*)(g_Weff + (size_t)(1*N_ + n)*KD);
                float4* d0 = (float4*)Wst;
                float4* d1 = (float4*)(Wst + KD);
                for (int idx = tid; idx < KD/4; idx += BLOCK) { d0[idx] = sr[idx]; d1[idx] = su[idx]; }
            }
            __syncthreads();

            const int nB = *pnB;
            const int BG = (nB + 1) >> 1;

            // r/u pass: thread tile = 2 batches x 8 dims, gate as task dim
            for (int tt = tid; tt < 2*BG*8; tt += BLOCK) {
                int g   = (tt >= BG*8) ? 1 : 0;
                int rem = tt - g*BG*8;
                int dg  = rem & 7;
                int bg  = rem >> 3;
                int b0 = listB[bg*2];
                int b1 = listB[min(bg*2 + 1, nB - 1)];
                const float* W   = Wst + g*KD + dg*8;
                const float* c0p = combs + b0*K2;
                const float* c1p = combs + b1*K2;
                const float* bb  = g_beff + (g*N_ + n)*D_ + dg*8;
                float4 p0 = *(const float4*)(bb);
                float4 p1 = *(const float4*)(bb + 4);
                float4 q0 = p0, q1 = p1;  // acc for b1
                #pragma unroll 3
                for (int k = 0; k < K2; k++) {
                    float c0 = c0p[k], c1 = c1p[k];
                    float4 w0 = *(const float4*)(W + k*64);
                    float4 w1 = *(const float4*)(W + k*64 + 4);
                    p0.x = fmaf(c0, w0.x, p0.x); p0.y = fmaf(c0, w0.y, p0.y);
                    p0.z = fmaf(c0, w0.z, p0.z); p0.w = fmaf(c0, w0.w, p0.w);
                    p1.x = fmaf(c0, w1.x, p1.x); p1.y = fmaf(c0, w1.y, p1.y);
                    p1.z = fmaf(c0, w1.z, p1.z); p1.w = fmaf(c0, w1.w, p1.w);
                    q0.x = fmaf(c1, w0.x, q0.x); q0.y = fmaf(c1, w0.y, q0.y);
                    q0.z = fmaf(c1, w0.z, q0.z); q0.w = fmaf(c1, w0.w, q0.w);
                    q1.x = fmaf(c1, w1.x, q1.x); q1.y = fmaf(c1, w1.y, q1.y);
                    q1.z = fmaf(c1, w1.z, q1.z); q1.w = fmaf(c1, w1.w, q1.w);
                }
                float rp[8] = {p0.x,p0.y,p0.z,p0.w,p1.x,p1.y,p1.z,p1.w};
                float rq[8] = {q0.x,q0.y,q0.z,q0.w,q1.x,q1.y,q1.z,q1.w};
                if (g == 0) {
                    #pragma unroll
                    for (int j = 0; j < 8; j++) {
                        int d = dg*8 + j;
                        zcs[b0*K2 + 65 + d] = sigmoidf_(rp[j]) * hs[b0*64 + d];
                        zcs[b1*K2 + 65 + d] = sigmoidf_(rq[j]) * hs[b1*64 + d];
                    }
                } else {
                    #pragma unroll
                    for (int j = 0; j < 8; j++) {
                        int d = dg*8 + j;
                        us[b0*64 + d] = sigmoidf_(rp[j]);
                        us[b1*64 + d] = sigmoidf_(rq[j]);
                    }
                }
            }
            __syncthreads();
            // stage Wc (overwrites Wr region)
            {
                const float4* sc = (const float4*)(g_Weff + (size_t)(2*N_ + n)*KD);
                float4* d0 = (float4*)Wst;
                for (int idx = tid; idx < KD/4; idx += BLOCK) d0[idx] = sc[idx];
            }
            __syncthreads();

            // candidate pass: thread tile = 2 batches x 4 dims
            for (int tt = tid; tt < BG*16; tt += BLOCK) {
                int dg = tt & 15;
                int bg = tt >> 4;
                int b0 = listB[bg*2];
                int b1 = listB[min(bg*2 + 1, nB - 1)];
                const float* W   = Wst + dg*4;
                const float* z0p = zcs + b0*K2;
                const float* z1p = zcs + b1*K2;
                float4 bias = *(const float4*)(g_beff + (size_t)(2*N_ + n)*D_ + dg*4);
                float4 a0 = bias, a1 = bias;
                #pragma unroll 3
                for (int k = 0; k < K2; k++) {
                    float z0 = z0p[k], z1 = z1p[k];
                    float4 w = *(const float4*)(W + k*64);
                    a0.x = fmaf(z0, w.x, a0.x); a0.y = fmaf(z0, w.y, a0.y);
                    a0.z = fmaf(z0, w.z, a0.z); a0.w = fmaf(z0, w.w, a0.w);
                    a1.x = fmaf(z1, w.x, a1.x); a1.y = fmaf(z1, w.y, a1.y);
                    a1.z = fmaf(z1, w.z, a1.z); a1.w = fmaf(z1, w.w, a1.w);
                }
                float ca[4] = {a0.x, a0.y, a0.z, a0.w};
                float cb[4] = {a1.x, a1.y, a1.z, a1.w};
                float h2a[4], h2b[4];
                #pragma unroll
                for (int j = 0; j < 4; j++) {
                    int d = dg*4 + j;
                    float h1a = zcs[b0*K2 + 65 + d];
                    float h1b = zcs[b1*K2 + 65 + d];
                    float ua  = us[b0*64 + d];
                    float ub  = us[b1*64 + d];
                    h2a[j] = h1a + ua * (tanhf(ca[j]) - h1a);
                    h2b[j] = h1b + ub * (tanhf(cb[j]) - h1b);
                }
                float4 va = make_float4(h2a[0], h2a[1], h2a[2], h2a[3]);
                float4 vb = make_float4(h2b[0], h2b[1], h2b[2], h2b[3]);
                *(float4*)&hnext[(b0*N_ + n)*D_ + dg*4] = va;
                *(float4*)&hnext[(b1*N_ + n)*D_ + dg*4] = vb;
                if (t == lenS[b0] - 1) *(float4*)&out[(b0*N_ + n)*D_ + dg*4] = va;
                if (t == lenS[b1] - 1) *(float4*)&out[(b1*N_ + n)*D_ + dg*4] = vb;
            }
            // unobserved batches: carry h through
            for (int idx = tid; idx < B_*D_; idx += BLOCK) {
                int b = idx >> 6, d = idx & 63;
                if (ms[b] == 0.0f) {
                    float v = hs[idx];
                    hnext[(b*N_ + n)*D_ + d] = v;
                    if (t == lenS[b] - 1) out[(b*N_ + n)*D_ + d] = v;
                }
            }
        }
        grid_barrier();
    }
}

extern "C" void kernel_launch(void* const* d_in, const int* in_sizes, int n_in,
                              void* d_out, int out_size) {
    const float* obs     = (const float*)d_in[0];
    const float* mask    = (const float*)d_in[2];
    const int*   lengths = (const int*)d_in[5];
    const float* avg     = (const float*)d_in[6];
    const float* vpe     = (const float*)d_in[7];
    const float* rarW    = (const float*)d_in[8];
    const float* adjI    = (const float*)d_in[9];
    const float* W1      = (const float*)d_in[10];
    const float* b1      = (const float*)d_in[11];
    const float* W2      = (const float*)d_in[12];
    const float* b2      = (const float*)d_in[13];
    const float* Wu      = (const float*)d_in[14];
    const float* bu      = (const float*)d_in[15];
    const float* Wr      = (const float*)d_in[16];
    const float* br      = (const float*)d_in[17];
    const float* Wc      = (const float*)d_in[18];
    const float* bc      = (const float*)d_in[19];
    float* out = (float*)d_out;

    cudaFuncSetAttribute(cgrnn_persistent,
                         cudaFuncAttributeMaxDynamicSharedMemorySize, SMEM_BYTES);
    cgrnn_persistent<<<GRID, BLOCK, SMEM_BYTES>>>(
        obs, mask, lengths, avg, vpe, rarW, adjI,
        W1, b1, W2, b2, Wr, br, Wu, bu, Wc, bc, out);
}

// round 3
// speedup vs baseline: 2.1188x; 1.3129x over previous
#include <cuda_runtime.h>
#include <cuda_bf16.h>
#include <math.h>

#define B_ 32
#define T_ 64
#define N_ 128
#define D_ 64
#define K2 129            // 2D+1
#define KD (K2*D_)        // 8256
#define HSZ (B_*N_*D_)    // 262144
#define GRID 128
#define BLOCK 512

// smem layout (floats)
#define OFF_W     0                  // 3*KD = 24768 (persistent Weff r,u,c)
#define OFF_BEFF  (3*KD)             // 192  (persistent beff)
#define OFF_S     (3*KD + 192)       // scratch union base = 24960
// Phase A scratch (rel. to OFF_S)
#define A_FEAT    0                  // 128*132 = 16896
#define A_WT      16896              // 128*32  = 4096
#define A_RSV     20992              // 128
#define A_MV      21120              // 128
#define A_LIST    21248              // 128 ints
#define A_CNT     21376              // 8 ints (4 cnt + 4 masks)
// Phase B scratch (rel. to OFF_S)
#define B_COMB    0                  // 32*129 = 4128
#define B_ZCS     4128               // 32*129 = 4128  (x 0..64 | h1 65..128)
#define B_HS      8256               // 32*64  = 2048
#define B_US      10304              // 32*64  = 2048
#define B_MS      12352              // 32
#define B_LISTB   12384              // 32 ints
#define B_LEN     12416              // 32 ints
#define B_PNB     12448              // 1 int
#define SMEM_FLOATS (OFF_S + 21384)  // 46344 floats = 185376 B
#define SMEM_BYTES  (SMEM_FLOATS*4 + 256)

__device__ float g_invtot[B_*N_];
__device__ float g_hbuf[2*HSZ];
__device__ float g_comb[B_*N_*K2];

__device__ unsigned int g_bar_cnt = 0;
__device__ volatile unsigned int g_bar_gen = 0;

__device__ __forceinline__ void grid_barrier() {
    __syncthreads();
    if (threadIdx.x == 0) {
        __threadfence();
        unsigned int gen = g_bar_gen;
        if (atomicAdd(&g_bar_cnt, 1u) == GRID - 1u) {
            g_bar_cnt = 0;
            __threadfence();
            g_bar_gen = gen + 1u;
        } else {
            while (g_bar_gen == gen) { }
            __threadfence();
        }
    }
    __syncthreads();
}

__device__ __forceinline__ float sigmoidf_(float x) {
    return 1.0f / (1.0f + __expf(-x));
}

__global__ void __launch_bounds__(BLOCK, 1)
cgrnn_persistent(const float* __restrict__ obs,      // [B,T,N,D]
                 const float* __restrict__ mask,     // [B,T,N]
                 const int*   __restrict__ lengths,  // [B]
                 const float* __restrict__ avg,      // [B,T,N]
                 const float* __restrict__ vpe,      // [N,768]
                 const float* __restrict__ rarW,     // [N,N]
                 const float* __restrict__ adjI,     // [N,N]
                 const float* __restrict__ W1,       // [768,128]
                 const float* __restrict__ b1,       // [128]
                 const float* __restrict__ W2,       // [128,5]
                 const float* __restrict__ b2,       // [5]
                 const float* __restrict__ Wr, const float* __restrict__ brp,
                 const float* __restrict__ Wu, const float* __restrict__ bup,
                 const float* __restrict__ Wc, const float* __restrict__ bcp,
                 float* __restrict__ out)            // [B,N,D]
{
    extern __shared__ char smem_raw[];
    float* sm = (float*)smem_raw;
    float* Wst    = sm + OFF_W;
    float* beff_s = sm + OFF_BEFF;
    float* scr    = sm + OFF_S;
    const int tid = threadIdx.x;
    const int bid = blockIdx.x;
    const int n_node = bid;   // Phase B / init node binding

    // ========== P1: hypernetwork vv for this node (into scr) ==========
    {
        float* part = scr;           // 512
        float* hid  = scr + 512;     // 128
        float* vvs  = scr + 640;     // 5
        int q = tid >> 7, col = tid & 127;
        float acc = 0.0f;
        int k0 = q * 192;
        const float* vrow = vpe + n_node*768;
        #pragma unroll 4
        for (int k = k0; k < k0 + 192; k++)
            acc = fmaf(vrow[k], W1[k*128 + col], acc);
        part[tid] = acc;
        __syncthreads();
        if (tid < 128) {
            float h = part[tid] + part[128+tid] + part[256+tid] + part[384+tid] + b1[tid];
            hid[tid] = fmaxf(h, 0.0f);
        }
        __syncthreads();
        if (tid < 5) {
            float a = b2[tid];
            for (int d = 0; d < 128; d++)
                a = fmaf(hid[d], W2[d*5 + tid], a);
            vvs[tid] = a;
        }
        __syncthreads();

        // ===== P2a: effective weights for this node, directly into smem =====
        float v0 = vvs[0], v1 = vvs[1], v2 = vvs[2], v3 = vvs[3], v4 = vvs[4];
        for (int idx = tid; idx < 3*KD; idx += BLOCK) {
            int g = idx / KD;
            int kd = idx - g*KD;
            const float* src = (g == 0) ? Wr : (g == 1) ? Wu : Wc;
            float a = v0 * src[kd];
            a = fmaf(v1, src[KD + kd], a);
            a = fmaf(v2, src[2*KD + kd], a);
            a = fmaf(v3, src[3*KD + kd], a);
            a = fmaf(v4, src[4*KD + kd], a);
            Wst[idx] = a;
        }
        for (int idx = tid; idx < 3*D_; idx += BLOCK) {
            int g = idx >> 6;
            int d = idx & 63;
            const float* src = (g == 0) ? brp : (g == 1) ? bup : bcp;
            float a = v0 * src[d];
            a = fmaf(v1, src[D_ + d], a);
            a = fmaf(v2, src[2*D_ + d], a);
            a = fmaf(v3, src[3*D_ + d], a);
            a = fmaf(v4, src[4*D_ + d], a);
            beff_s[idx] = a;
        }
    }

    // ===== P2b: inv_tot + zero h0 (global, cooperative) =====
    {
        for (int k = tid; k < 32; k += BLOCK) {
            int idx = bid*32 + k;
            int b = idx >> 7;
            int n = idx & 127;
            float s = 0.0f;
            for (int t = 0; t < T_; t++) s += mask[(b*T_ + t)*N_ + n];
            g_invtot[idx] = 1.0f / (s + 1.0f);
        }
        for (int idx = bid*BLOCK + tid; idx < HSZ; idx += GRID*BLOCK)
            g_hbuf[idx] = 0.0f;
    }
    grid_barrier();

    // ========== time loop ==========
    for (int t = 0; t < T_; t++) {
        const float* hprev = g_hbuf + (t & 1) * HSZ;
        float*       hnext = g_hbuf + ((t + 1) & 1) * HSZ;

        // ---------------- Phase A ----------------
        {
            const int b = bid >> 2;
            const int q = bid & 3;
            float* feat = scr + A_FEAT;
            float* wT   = scr + A_WT;
            float* rsv  = scr + A_RSV;
            float* mv   = scr + A_MV;
            int*   list = (int*)(scr + A_LIST);
            int*   cnt  = (int*)(scr + A_CNT);       // [0..3] counts, [4..7] masks

            if (tid < 128) {
                float m = mask[(b*T_ + t)*N_ + tid];
                mv[tid]  = m;
                rsv[tid] = 0.5f * tanhf(avg[(b*T_ + t)*N_ + tid] * g_invtot[b*N_ + tid]);
                bool ob = (m != 0.0f);
                unsigned msk = __ballot_sync(0xffffffffu, ob);
                int w = tid >> 5, lane = tid & 31;
                if (lane == 0) { cnt[w] = __popc(msk); ((unsigned*)cnt)[4 + w] = msk; }
            }
            __syncthreads();
            const int nobs = cnt[0] + cnt[1] + cnt[2] + cnt[3];
            if (tid < 128) {
                int w = tid >> 5, lane = tid & 31;
                unsigned msk = ((unsigned*)cnt)[4 + w];
                if ((msk >> lane) & 1u) {
                    int off = __popc(msk & ((1u << lane) - 1u));
                    for (int ww = 0; ww < w; ww++) off += cnt[ww];
                    list[off] = tid;
                }
            }
            __syncthreads();

            const int lo  = (nobs * q) >> 2;
            const int hi  = (nobs * (q + 1)) >> 2;
            const int myn = hi - lo;

            // stage feat rows for observed j
            for (int idx = tid; idx < nobs*132; idx += BLOCK) {
                int jc = idx / 132;
                int f  = idx - jc*132;
                int j  = list[jc];
                float v = 0.0f;
                if (f < 64)       v = obs[((b*T_ + t)*N_ + j)*D_ + f];
                else if (f == 64) v = rsv[j];
                else if (f < 129) v = hprev[(b*N_ + j)*D_ + (f - 65)];
                feat[idx] = v;
            }
            // stage wT[jc][ic] (ic = local row, zero-padded to 32)
            {
                int ic = tid >> 4;
                int i  = (ic < myn) ? list[lo + ic] : -1;
                float rsi = (ic < myn) ? rsv[i] : 0.0f;
                for (int jc = (tid & 15); jc < nobs; jc += 16) {
                    float wv = 0.0f;
                    if (ic < myn) {
                        int j = list[jc];
                        if (j == i) wv = 1.0f;
                        else wv = adjI[i*N_ + j] *
                                  (1.0f - rarW[i*N_ + j] * fabsf(rsi - rsv[j]));
                    }
                    wT[jc*32 + ic] = wv;
                }
            }
            __syncthreads();

            const int RG = (myn + 3) >> 2;
            for (int tt = tid; tt < RG*129; tt += BLOCK) {
                int rg = tt / 129;
                int c  = tt - rg*129;
                const float* wp = wT + rg*4;
                const float* fp = feat + c;
                float4 a = make_float4(0.f, 0.f, 0.f, 0.f);
                #pragma unroll 2
                for (int jc = 0; jc < nobs; jc++) {
                    float fv  = fp[jc*132];
                    float4 w4 = *(const float4*)(wp + jc*32);
                    a.x = fmaf(w4.x, fv, a.x);
                    a.y = fmaf(w4.y, fv, a.y);
                    a.z = fmaf(w4.z, fv, a.z);
                    a.w = fmaf(w4.w, fv, a.w);
                }
                int icb = rg*4;
                float av[4] = {a.x, a.y, a.z, a.w};
                #pragma unroll
                for (int r = 0; r < 4; r++) {
                    if (icb + r < myn) {
                        int i = list[lo + icb + r];
                        g_comb[(b*N_ + i)*K2 + c] = av[r];
                    }
                }
            }
        }
        grid_barrier();

        // ---------------- Phase B ----------------
        {
            const int n = n_node;
            float* combs = scr + B_COMB;
            float* zcs   = scr + B_ZCS;
            float* hs    = scr + B_HS;
            float* us    = scr + B_US;
            float* ms    = scr + B_MS;
            int*   listB = (int*)(scr + B_LISTB);
            int*   lenS  = (int*)(scr + B_LEN);
            int*   pnB   = (int*)(scr + B_PNB);

            if (tid < 32) {
                int b = tid;
                float m = mask[(b*T_ + t)*N_ + n];
                ms[b] = m;
                zcs[b*K2 + 64] = 0.5f * tanhf(avg[(b*T_ + t)*N_ + n] * g_invtot[b*N_ + n]);
                lenS[b] = lengths[b];
                bool ob = (m != 0.0f);
                unsigned msk = __ballot_sync(0xffffffffu, ob);
                if (ob) listB[__popc(msk & ((1u << tid) - 1u))] = b;
                if (tid == 0) *pnB = __popc(msk);
            }
            for (int idx = tid; idx < B_*D_; idx += BLOCK) {
                int b = idx >> 6, d = idx & 63;
                hs[idx] = hprev[(b*N_ + n)*D_ + d];
            }
            __syncthreads();
            const int nB = *pnB;

            // stage comb + x for observed batches
            for (int idx = tid; idx < nB*K2; idx += BLOCK) {
                int bc = idx / K2;
                int k  = idx - bc*K2;
                int b  = listB[bc];
                combs[b*K2 + k] = g_comb[(b*N_ + n)*K2 + k];
            }
            for (int idx = tid; idx < nB*D_; idx += BLOCK) {
                int bc = idx >> 6, d = idx & 63;
                int b  = listB[bc];
                zcs[b*K2 + d] = obs[((b*T_ + t)*N_ + n)*D_ + d];
            }
            __syncthreads();

            // r/u pass: tile = 1 batch x 4 dims, gates stacked
            {
                const int NG = nB * 16;
                for (int tt = tid; tt < 2*NG; tt += BLOCK) {
                    int g   = (tt >= NG) ? 1 : 0;
                    int rem = tt - g*NG;
                    int bc  = rem >> 4;
                    int dg  = rem & 15;
                    int b   = listB[bc];
                    const float* W  = Wst + g*KD + dg*4;
                    const float* cb = combs + b*K2;
                    float4 a = *(const float4*)(beff_s + g*D_ + dg*4);
                    #pragma unroll 4
                    for (int k = 0; k < K2; k++) {
                        float c = cb[k];
                        float4 w = *(const float4*)(W + k*64);
                        a.x = fmaf(c, w.x, a.x);
                        a.y = fmaf(c, w.y, a.y);
                        a.z = fmaf(c, w.z, a.z);
                        a.w = fmaf(c, w.w, a.w);
                    }
                    int d0 = dg*4;
                    if (g == 0) {
                        zcs[b*K2 + 65 + d0 + 0] = sigmoidf_(a.x) * hs[b*64 + d0 + 0];
                        zcs[b*K2 + 65 + d0 + 1] = sigmoidf_(a.y) * hs[b*64 + d0 + 1];
                        zcs[b*K2 + 65 + d0 + 2] = sigmoidf_(a.z) * hs[b*64 + d0 + 2];
                        zcs[b*K2 + 65 + d0 + 3] = sigmoidf_(a.w) * hs[b*64 + d0 + 3];
                    } else {
                        us[b*64 + d0 + 0] = sigmoidf_(a.x);
                        us[b*64 + d0 + 1] = sigmoidf_(a.y);
                        us[b*64 + d0 + 2] = sigmoidf_(a.z);
                        us[b*64 + d0 + 3] = sigmoidf_(a.w);
                    }
                }
            }
            __syncthreads();

            // candidate pass: tile = 1 batch x 2 dims
            {
                const float* Wc_s = Wst + 2*KD;
                for (int tt = tid; tt < nB*32; tt += BLOCK) {
                    int bc  = tt >> 5;
                    int dg2 = tt & 31;
                    int b   = listB[bc];
                    int d0  = dg2*2;
                    const float* zb = zcs + b*K2;
                    float ax = beff_s[2*D_ + d0];
                    float ay = beff_s[2*D_ + d0 + 1];
                    const float* W = Wc_s + d0;
                    #pragma unroll 4
                    for (int k = 0; k < K2; k++) {
                        float z = zb[k];
                        float2 w = *(const float2*)(W + k*64);
                        ax = fmaf(z, w.x, ax);
                        ay = fmaf(z, w.y, ay);
                    }
                    float h1x = zb[65 + d0], h1y = zb[65 + d0 + 1];
                    float ux = us[b*64 + d0], uy = us[b*64 + d0 + 1];
                    float h2x = h1x + ux * (tanhf(ax) - h1x);
                    float h2y = h1y + uy * (tanhf(ay) - h1y);
                    float2 v = make_float2(h2x, h2y);
                    *(float2*)&hnext[(b*N_ + n)*D_ + d0] = v;
                    if (t == lenS[b] - 1)
                        *(float2*)&out[(b*N_ + n)*D_ + d0] = v;
                }
            }
            // unobserved: carry h
            for (int idx = tid; idx < B_*D_; idx += BLOCK) {
                int b = idx >> 6, d = idx & 63;
                if (ms[b] == 0.0f) {
                    float v = hs[idx];
                    hnext[(b*N_ + n)*D_ + d] = v;
                    if (t == lenS[b] - 1) out[(b*N_ + n)*D_ + d] = v;
                }
            }
        }
        grid_barrier();
    }
}

extern "C" void kernel_launch(void* const* d_in, const int* in_sizes, int n_in,
                              void* d_out, int out_size) {
    const float* obs     = (const float*)d_in[0];
    const float* mask    = (const float*)d_in[2];
    const int*   lengths = (const int*)d_in[5];
    const float* avg     = (const float*)d_in[6];
    const float* vpe     = (const float*)d_in[7];
    const float* rarW    = (const float*)d_in[8];
    const float* adjI    = (const float*)d_in[9];
    const float* W1      = (const float*)d_in[10];
    const float* b1      = (const float*)d_in[11];
    const float* W2      = (const float*)d_in[12];
    const float* b2      = (const float*)d_in[13];
    const float* Wu      = (const float*)d_in[14];
    const float* bu      = (const float*)d_in[15];
    const float* Wr      = (const float*)d_in[16];
    const float* br      = (const float*)d_in[17];
    const float* Wc      = (const float*)d_in[18];
    const float* bc      = (const float*)d_in[19];
    float* out = (float*)d_out;

    cudaFuncSetAttribute(cgrnn_persistent,
                         cudaFuncAttributeMaxDynamicSharedMemorySize, SMEM_BYTES);
    cgrnn_persistent<<<GRID, BLOCK, SMEM_BYTES>>>(
        obs, mask, lengths, avg, vpe, rarW, adjI,
        W1, b1, W2, b2, Wr, br, Wu, bu, Wc, bc, out);
}

// round 4
// speedup vs baseline: 2.3010x; 1.0860x over previous
#include <cuda_runtime.h>
#include <cuda_bf16.h>
#include <math.h>

#define B_ 32
#define T_ 64
#define N_ 128
#define D_ 64
#define K2 129            // 2D+1
#define KD (K2*D_)        // 8256
#define HSZ (B_*N_*D_)    // 262144
#define GRID 128
#define BLOCK 1024

// ---- smem layout (floats) ----
#define OFF_W     0                  // 3*KD persistent Weff (r,u,c), permuted k-order [x|h|rs]
#define OFF_BEFF  (3*KD)             // 192
#define OFF_S     (3*KD + 192)
// Phase A scratch (rel. OFF_S): feat rows [x(0..63)|h(64..127)|rs(128)] stride 132
#define A_FEAT    0                  // 128*132 = 16896
#define A_WT      16896              // 128*32  = 4096
#define A_RSV     20992              // 128
#define A_LIST    21120              // 128 ints
#define A_CNT     21248              // 8 ints
// Phase B scratch (rel. OFF_S)
#define B_COMB    0                  // 32*129 = 4128
#define B_ZCS     4128               // 32*132 = 4224 (x 0..63 | h1 64..127 | rs 128)
#define B_HS      8352               // 2048
#define B_US      10400              // 2048
#define B_MS      12448              // 32
#define B_LISTB   12480              // 32 ints
#define B_LEN     12512              // 32 ints
#define B_PNB     12544              // 1
#define SCR_FLOATS 21260
#define SMEM_FLOATS (OFF_S + SCR_FLOATS)
#define SMEM_BYTES  (SMEM_FLOATS*4 + 128)

__device__ float g_invtot[B_*N_];
__device__ float g_hbuf[2*HSZ];
__device__ float g_comb[B_*N_*K2];
__device__ float g_P[N_*N_];   // P[j][i] = adjI[i][j]
__device__ float g_Q[N_*N_];   // Q[j][i] = adjI[i][j]*rarW[i][j]

// ---- two-level grid barrier (monotonic counters) ----
__device__ unsigned int g_cnt[8*32];   // 128B-spaced group counters
__device__ unsigned int g_rootc;
__device__ volatile unsigned int g_gen;

__device__ __forceinline__ void grid_barrier() {
    __syncthreads();
    if (threadIdx.x == 0) {
        __threadfence();
        unsigned int gen = g_gen;
        unsigned int grp = blockIdx.x >> 4;
        unsigned int o = atomicAdd(&g_cnt[grp*32], 1u);
        if ((o & 15u) == 15u) {
            unsigned int r = atomicAdd(&g_rootc, 1u);
            if ((r & 7u) == 7u) {
                __threadfence();
                g_gen = gen + 1u;
            }
        }
        while (g_gen == gen) { }
        __threadfence();
    }
    __syncthreads();
}

__device__ __forceinline__ float sigmoidf_(float x) {
    return 1.0f / (1.0f + __expf(-x));
}
__device__ __forceinline__ float tanhfast(float x) {
    float y;
    asm("tanh.approx.f32 %0, %1;" : "=f"(y) : "f"(x));
    return y;
}

__global__ void __launch_bounds__(BLOCK, 1)
cgrnn_persistent(const float* __restrict__ obs,      // [B,T,N,D]
                 const float* __restrict__ mask,     // [B,T,N]
                 const int*   __restrict__ lengths,  // [B]
                 const float* __restrict__ avg,      // [B,T,N]
                 const float* __restrict__ vpe,      // [N,768]
                 const float* __restrict__ rarW,     // [N,N]
                 const float* __restrict__ adjI,     // [N,N]
                 const float* __restrict__ W1,       // [768,128]
                 const float* __restrict__ b1,       // [128]
                 const float* __restrict__ W2,       // [128,5]
                 const float* __restrict__ b2,       // [5]
                 const float* __restrict__ Wr, const float* __restrict__ brp,
                 const float* __restrict__ Wu, const float* __restrict__ bup,
                 const float* __restrict__ Wc, const float* __restrict__ bcp,
                 float* __restrict__ out)            // [B,N,D]
{
    extern __shared__ char smem_raw[];
    float* sm = (float*)smem_raw;
    float* Wst    = sm + OFF_W;
    float* beff_s = sm + OFF_BEFF;
    float* scr    = sm + OFF_S;
    const int tid = threadIdx.x;
    const int bid = blockIdx.x;
    const int n_node = bid;

    // ========== P1: hypernetwork vv for this node ==========
    {
        float* part = scr;           // 1024
        float* hid  = scr + 1024;    // 128
        float* vvs  = scr + 1152;    // 5
        int q = tid >> 7, col = tid & 127;
        const float* vrow = vpe + n_node*768;
        float acc = 0.0f;
        int k0 = q * 96;
        #pragma unroll 4
        for (int k = k0; k < k0 + 96; k++)
            acc = fmaf(vrow[k], W1[k*128 + col], acc);
        part[tid] = acc;
        __syncthreads();
        if (tid < 128) {
            float h = b1[tid];
            #pragma unroll
            for (int qq = 0; qq < 8; qq++) h += part[qq*128 + tid];
            hid[tid] = fmaxf(h, 0.0f);
        }
        __syncthreads();
        if (tid < 5) {
            float a = b2[tid];
            for (int d = 0; d < 128; d++)
                a = fmaf(hid[d], W2[d*5 + tid], a);
            vvs[tid] = a;
        }
        __syncthreads();

        // ===== P2a: effective weights (k-order permuted to [x|h|rs]) =====
        float v0 = vvs[0], v1 = vvs[1], v2 = vvs[2], v3 = vvs[3], v4 = vvs[4];
        for (int idx = tid; idx < 3*KD; idx += BLOCK) {
            int g = idx / KD;
            int kd = idx - g*KD;
            int k = kd >> 6;
            int d = kd & 63;
            int ko = (k < 64) ? k : ((k < 128) ? (k + 1) : 64);
            const float* src = (g == 0) ? Wr : (g == 1) ? Wu : Wc;
            int off = ko*64 + d;
            float a = v0 * src[off];
            a = fmaf(v1, src[KD + off], a);
            a = fmaf(v2, src[2*KD + off], a);
            a = fmaf(v3, src[3*KD + off], a);
            a = fmaf(v4, src[4*KD + off], a);
            Wst[idx] = a;
        }
        for (int idx = tid; idx < 3*D_; idx += BLOCK) {
            int g = idx >> 6;
            int d = idx & 63;
            const float* src = (g == 0) ? brp : (g == 1) ? bup : bcp;
            float a = v0 * src[d];
            a = fmaf(v1, src[D_ + d], a);
            a = fmaf(v2, src[2*D_ + d], a);
            a = fmaf(v3, src[3*D_ + d], a);
            a = fmaf(v4, src[4*D_ + d], a);
            beff_s[idx] = a;
        }
    }

    // ===== P2b: inv_tot, transpose P/Q, zero h0 =====
    {
        for (int k = tid; k < 32; k += BLOCK) {
            int idx = bid*32 + k;
            int b = idx >> 7;
            int n = idx & 127;
            float s = 0.0f;
            for (int t = 0; t < T_; t++) s += mask[(b*T_ + t)*N_ + n];
            g_invtot[idx] = 1.0f / (s + 1.0f);
        }
        for (int idx = bid*BLOCK + tid; idx < N_*N_; idx += GRID*BLOCK) {
            int j = idx >> 7, i = idx & 127;
            float a = adjI[i*N_ + j];
            g_P[idx] = a;
            g_Q[idx] = a * rarW[i*N_ + j];
        }
        for (int idx = bid*BLOCK + tid; idx < HSZ; idx += GRID*BLOCK)
            g_hbuf[idx] = 0.0f;
    }
    grid_barrier();

    // ========== time loop ==========
    for (int t = 0; t < T_; t++) {
        const float* hprev = g_hbuf + (t & 1) * HSZ;
        float*       hnext = g_hbuf + ((t + 1) & 1) * HSZ;

        // ---------------- Phase A: comb rows for observed nodes ----------------
        {
            const int b = bid >> 2;
            const int q = bid & 3;
            float* feat = scr + A_FEAT;
            float* wT   = scr + A_WT;
            float* rsv  = scr + A_RSV;
            int*   list = (int*)(scr + A_LIST);
            int*   cnt  = (int*)(scr + A_CNT);

            if (tid < 128) {
                float m = mask[(b*T_ + t)*N_ + tid];
                rsv[tid] = 0.5f * tanhfast(avg[(b*T_ + t)*N_ + tid] * g_invtot[b*N_ + tid]);
                bool ob = (m != 0.0f);
                unsigned msk = __ballot_sync(0xffffffffu, ob);
                int w = tid >> 5, lane = tid & 31;
                if (lane == 0) { cnt[w] = __popc(msk); ((unsigned*)cnt)[4 + w] = msk; }
            }
            __syncthreads();
            const int nobs = cnt[0] + cnt[1] + cnt[2] + cnt[3];
            if (tid < 128) {
                int w = tid >> 5, lane = tid & 31;
                unsigned msk = ((unsigned*)cnt)[4 + w];
                if ((msk >> lane) & 1u) {
                    int off = __popc(msk & ((1u << lane) - 1u));
                    for (int ww = 0; ww < w; ww++) off += cnt[ww];
                    list[off] = tid;
                }
            }
            __syncthreads();

            const int lo  = (nobs * q) >> 2;
            const int hi  = (nobs * (q + 1)) >> 2;
            const int myn = hi - lo;

            // stage feat (float4, aligned): x then h, then rs
            for (int idx = tid; idx < nobs*16; idx += BLOCK) {
                int jc = idx >> 4, qq = idx & 15;
                int j = list[jc];
                *(float4*)(feat + jc*132 + qq*4) =
                    *(const float4*)(obs + (size_t)((b*T_ + t)*N_ + j)*D_ + qq*4);
            }
            for (int idx = tid; idx < nobs*16; idx += BLOCK) {
                int jc = idx >> 4, qq = idx & 15;
                int j = list[jc];
                *(float4*)(feat + jc*132 + 64 + qq*4) =
                    *(const float4*)(hprev + (size_t)(b*N_ + j)*D_ + qq*4);
            }
            if (tid < nobs) feat[tid*132 + 128] = rsv[list[tid]];

            // stage wT[jc][ic]: lane = ic (conflict-free), coalesced P/Q loads
            {
                int jc0  = tid >> 5;
                int ic   = tid & 31;
                int i    = (ic < myn) ? list[lo + ic] : 0;
                float rsi = rsv[i];
                bool valid = (ic < myn);
                for (int jc = jc0; jc < nobs; jc += 32) {
                    int j = list[jc];
                    float wv = 0.0f;
                    if (valid) {
                        if (j == i) wv = 1.0f;
                        else wv = g_P[j*N_ + i] - g_Q[j*N_ + i] * fabsf(rsi - rsv[j]);
                    }
                    wT[jc*32 + ic] = wv;
                }
            }
            __syncthreads();

            // main GEMM: 2-row x 1-col tiles -> RG2*129 tasks
            const int RG2 = (myn + 1) >> 1;
            for (int tt = tid; tt < RG2*129; tt += BLOCK) {
                int rg = tt / 129;
                int c  = tt - rg*129;
                const float* wp = wT + rg*2;
                const float* fp = feat + c;
                float ax = 0.0f, ay = 0.0f;
                #pragma unroll 4
                for (int jc = 0; jc < nobs; jc++) {
                    float fv = fp[jc*132];
                    float2 w2 = *(const float2*)(wp + jc*32);
                    ax = fmaf(w2.x, fv, ax);
                    ay = fmaf(w2.y, fv, ay);
                }
                int ic0 = rg*2;
                {
                    int i = list[lo + ic0];
                    g_comb[(size_t)(b*N_ + i)*K2 + c] = ax;
                }
                if (ic0 + 1 < myn) {
                    int i = list[lo + ic0 + 1];
                    g_comb[(size_t)(b*N_ + i)*K2 + c] = ay;
                }
            }
        }
        grid_barrier();

        // ---------------- Phase B: gates + state update (block = node) ----------------
        {
            const int n = n_node;
            float* combs = scr + B_COMB;
            float* zcs   = scr + B_ZCS;
            float* hs    = scr + B_HS;
            float* us    = scr + B_US;
            float* ms    = scr + B_MS;
            int*   listB = (int*)(scr + B_LISTB);
            int*   lenS  = (int*)(scr + B_LEN);
            int*   pnB   = (int*)(scr + B_PNB);

            if (tid < 32) {
                int b = tid;
                float m = mask[(b*T_ + t)*N_ + n];
                ms[b] = m;
                zcs[b*132 + 128] = 0.5f * tanhfast(avg[(b*T_ + t)*N_ + n] * g_invtot[b*N_ + n]);
                lenS[b] = lengths[b];
                bool ob = (m != 0.0f);
                unsigned msk = __ballot_sync(0xffffffffu, ob);
                if (ob) listB[__popc(msk & ((1u << tid) - 1u))] = b;
                if (tid == 0) *pnB = __popc(msk);
            }
            for (int idx = tid; idx < (B_*D_)/4; idx += BLOCK) {
                int b = idx >> 4, qq = idx & 15;
                *(float4*)(hs + b*64 + qq*4) =
                    *(const float4*)(hprev + (size_t)(b*N_ + n)*D_ + qq*4);
            }
            __syncthreads();
            const int nB = *pnB;

            for (int idx = tid; idx < nB*K2; idx += BLOCK) {
                int bc = idx / K2;
                int k  = idx - bc*K2;
                int b  = listB[bc];
                combs[b*K2 + k] = g_comb[(size_t)(b*N_ + n)*K2 + k];
            }
            for (int idx = tid; idx < nB*16; idx += BLOCK) {
                int bc = idx >> 4, qq = idx & 15;
                int b  = listB[bc];
                *(float4*)(zcs + b*132 + qq*4) =
                    *(const float4*)(obs + (size_t)((b*T_ + t)*N_ + n)*D_ + qq*4);
            }
            __syncthreads();

            // r/u pass: 1 batch x 2 dims, gates stacked -> 2*nB*32 tasks
            {
                const int NG = nB * 32;
                for (int tt = tid; tt < 2*NG; tt += BLOCK) {
                    int g   = (tt >= NG) ? 1 : 0;
                    int rem = tt - g*NG;
                    int bc  = rem >> 5;
                    int d0  = (rem & 31) * 2;
                    int b   = listB[bc];
                    const float* W  = Wst + g*KD + d0;
                    const float* cb = combs + b*K2;
                    float2 acc = *(const float2*)(beff_s + g*D_ + d0);
                    #pragma unroll 3
                    for (int k = 0; k < K2; k++) {
                        float c = cb[k];
                        float2 w = *(const float2*)(W + k*64);
                        acc.x = fmaf(c, w.x, acc.x);
                        acc.y = fmaf(c, w.y, acc.y);
                    }
                    if (g == 0) {
                        zcs[b*132 + 64 + d0 + 0] = sigmoidf_(acc.x) * hs[b*64 + d0 + 0];
                        zcs[b*132 + 64 + d0 + 1] = sigmoidf_(acc.y) * hs[b*64 + d0 + 1];
                    } else {
                        us[b*64 + d0 + 0] = sigmoidf_(acc.x);
                        us[b*64 + d0 + 1] = sigmoidf_(acc.y);
                    }
                }
            }
            __syncthreads();

            // candidate pass: 1 batch x 1 dim -> nB*64 tasks
            {
                const float* Wc_s = Wst + 2*KD;
                for (int tt = tid; tt < nB*64; tt += BLOCK) {
                    int bc = tt >> 6;
                    int d  = tt & 63;
                    int b  = listB[bc];
                    const float* zb = zcs + b*132;
                    const float* W  = Wc_s + d;
                    float a = beff_s[2*D_ + d];
                    #pragma unroll 3
                    for (int k = 0; k < K2; k++)
                        a = fmaf(zb[k], W[k*64], a);
                    float h1 = zb[64 + d];
                    float u  = us[b*64 + d];
                    float h2 = h1 + u * (tanhfast(a) - h1);
                    hnext[(size_t)(b*N_ + n)*D_ + d] = h2;
                    if (t == lenS[b] - 1)
                        out[(size_t)(b*N_ + n)*D_ + d] = h2;
                }
            }
            // unobserved: carry h
            for (int idx = tid; idx < B_*D_; idx += BLOCK) {
                int b = idx >> 6, d = idx & 63;
                if (ms[b] == 0.0f) {
                    float v = hs[idx];
                    hnext[(size_t)(b*N_ + n)*D_ + d] = v;
                    if (t == lenS[b] - 1) out[(size_t)(b*N_ + n)*D_ + d] = v;
                }
            }
        }
        grid_barrier();
    }
}

extern "C" void kernel_launch(void* const* d_in, const int* in_sizes, int n_in,
                              void* d_out, int out_size) {
    const float* obs     = (const float*)d_in[0];
    const float* mask    = (const float*)d_in[2];
    const int*   lengths = (const int*)d_in[5];
    const float* avg     = (const float*)d_in[6];
    const float* vpe     = (const float*)d_in[7];
    const float* rarW    = (const float*)d_in[8];
    const float* adjI    = (const float*)d_in[9];
    const float* W1      = (const float*)d_in[10];
    const float* b1      = (const float*)d_in[11];
    const float* W2      = (const float*)d_in[12];
    const float* b2      = (const float*)d_in[13];
    const float* Wu      = (const float*)d_in[14];
    const float* bu      = (const float*)d_in[15];
    const float* Wr      = (const float*)d_in[16];
    const float* br      = (const float*)d_in[17];
    const float* Wc      = (const float*)d_in[18];
    const float* bc      = (const float*)d_in[19];
    float* out = (float*)d_out;

    cudaFuncSetAttribute(cgrnn_persistent,
                         cudaFuncAttributeMaxDynamicSharedMemorySize, SMEM_BYTES);
    cgrnn_persistent<<<GRID, BLOCK, SMEM_BYTES>>>(
        obs, mask, lengths, avg, vpe, rarW, adjI,
        W1, b1, W2, b2, Wr, br, Wu, bu, Wc, bc, out);
}

// round 6
// speedup vs baseline: 3.1666x; 1.3762x over previous
#include <cuda_runtime.h>
#include <cuda_bf16.h>
#include <math.h>

#define B_ 32
#define T_ 64
#define N_ 128
#define D_ 64
#define K2 129              // 2D+1 (source layout)
#define KD (K2*D_)          // 8256 (source stride)
#define KR 132              // padded k rows: [x 0..63 | rs 64 | pad 65..67 | h 68..131]
#define KD132 (KR*D_)       // 8448
#define HSZ (B_*N_*D_)
#define GRID 128
#define BLOCK 1024

// ---- smem layout (floats) ----
#define OFF_W     0                    // 3*KD132 persistent Weff (r,u,c)
#define OFF_BEFF  (3*KD132)            // 192
#define OFF_S     (3*KD132 + 192)
// Phase A scratch (rel OFF_S)
#define A_FEAT    0                    // 128*132 = 16896
#define A_WT      16896                // 128*32 = 4096
#define A_RSV     20992                // 128
#define A_LIST    21120                // 128 ints
#define A_CNT     21248                // 8 ints
// Phase B scratch (rel OFF_S)
#define B_COMB    0                    // 32*132 = 4224
#define B_ZCS     4224                 // 32*132 = 4224  (x|rs|pad|h1)
#define B_HS      8448                 // 2048
#define B_US      10496                // 2048
#define B_CX      12544                // 2048
#define B_MS      14592                // 32
#define B_LISTB   14624                // 32 ints
#define B_LEN     14656                // 32 ints
#define B_PNB     14688                // 1
#define SCR_FLOATS 21256
#define SMEM_FLOATS (OFF_S + SCR_FLOATS)
#define SMEM_BYTES  (SMEM_FLOATS*4 + 128)

__device__ float g_invtot[B_*N_];
__device__ float g_hbuf[2*HSZ];
__device__ float g_comb[B_*N_*KR];   // pad rows (65..67) never written; stay zero
__device__ float g_P[N_*N_];         // P[j][i] = adjI[i][j]
__device__ float g_Q[N_*N_];         // Q[j][i] = adjI[i][j]*rarW[i][j]

// ---- two-level grid barrier ----
__device__ unsigned int g_cnt[8*32];
__device__ unsigned int g_rootc;
__device__ volatile unsigned int g_gen;

__device__ __forceinline__ void grid_barrier() {
    __syncthreads();
    if (threadIdx.x == 0) {
        __threadfence();
        unsigned int gen = g_gen;
        unsigned int grp = blockIdx.x >> 4;
        unsigned int o = atomicAdd(&g_cnt[grp*32], 1u);
        if ((o & 15u) == 15u) {
            unsigned int r = atomicAdd(&g_rootc, 1u);
            if ((r & 7u) == 7u) {
                __threadfence();
                g_gen = gen + 1u;
            }
        }
        while (g_gen == gen) { }
        __threadfence();
    }
    __syncthreads();
}

__device__ __forceinline__ float tanhfast(float x) {
    float y;
    asm("tanh.approx.f32 %0, %1;" : "=f"(y) : "f"(x));
    return y;
}
__device__ __forceinline__ float sigfast(float x) {
    return fmaf(tanhfast(0.5f*x), 0.5f, 0.5f);
}

__global__ void __launch_bounds__(BLOCK, 1)
cgrnn_persistent(const float* __restrict__ obs,      // [B,T,N,D]
                 const float* __restrict__ mask,     // [B,T,N]
                 const int*   __restrict__ lengths,  // [B]
                 const float* __restrict__ avg,      // [B,T,N]
                 const float* __restrict__ vpe,      // [N,768]
                 const float* __restrict__ rarW,     // [N,N]
                 const float* __restrict__ adjI,     // [N,N]
                 const float* __restrict__ W1,       // [768,128]
                 const float* __restrict__ b1,       // [128]
                 const float* __restrict__ W2,       // [128,5]
                 const float* __restrict__ b2,       // [5]
                 const float* __restrict__ Wr, const float* __restrict__ brp,
                 const float* __restrict__ Wu, const float* __restrict__ bup,
                 const float* __restrict__ Wc, const float* __restrict__ bcp,
                 float* __restrict__ out)            // [B,N,D]
{
    extern __shared__ char smem_raw[];
    float* sm = (float*)smem_raw;
    float* Wst    = sm + OFF_W;
    float* beff_s = sm + OFF_BEFF;
    float* scr    = sm + OFF_S;
    const int tid  = threadIdx.x;
    const int bid  = blockIdx.x;
    const int warp = tid >> 5;
    const int lane = tid & 31;
    const int n_node = bid;

    // ========== P1: hypernetwork vv for this node ==========
    {
        float* part = scr;
        float* hid  = scr + 1024;
        float* vvs  = scr + 1152;
        int q = tid >> 7, col = tid & 127;
        const float* vrow = vpe + n_node*768;
        float acc = 0.0f;
        int k0 = q * 96;
        #pragma unroll 4
        for (int k = k0; k < k0 + 96; k++)
            acc = fmaf(vrow[k], W1[k*128 + col], acc);
        part[tid] = acc;
        __syncthreads();
        if (tid < 128) {
            float h = b1[tid];
            #pragma unroll
            for (int qq = 0; qq < 8; qq++) h += part[qq*128 + tid];
            hid[tid] = fmaxf(h, 0.0f);
        }
        __syncthreads();
        if (tid < 5) {
            float a = b2[tid];
            for (int d = 0; d < 128; d++)
                a = fmaf(hid[d], W2[d*5 + tid], a);
            vvs[tid] = a;
        }
        __syncthreads();

        // ===== P2a: effective weights in padded k-order [x|rs|pad3|h] =====
        float v0 = vvs[0], v1 = vvs[1], v2 = vvs[2], v3 = vvs[3], v4 = vvs[4];
        for (int idx = tid; idx < 3*KD132; idx += BLOCK) {
            int g  = idx / KD132;
            int kd = idx - g*KD132;
            int kk = kd >> 6;
            int d  = kd & 63;
            float a = 0.0f;
            if (kk < 65 || kk >= 68) {
                int ko = (kk < 65) ? kk : (kk - 3);
                const float* src = (g == 0) ? Wr : (g == 1) ? Wu : Wc;
                int off = ko*64 + d;
                a = v0 * src[off];
                a = fmaf(v1, src[KD + off], a);
                a = fmaf(v2, src[2*KD + off], a);
                a = fmaf(v3, src[3*KD + off], a);
                a = fmaf(v4, src[4*KD + off], a);
            }
            Wst[idx] = a;
        }
        for (int idx = tid; idx < 3*D_; idx += BLOCK) {
            int g = idx >> 6;
            int d = idx & 63;
            const float* src = (g == 0) ? brp : (g == 1) ? bup : bcp;
            float a = v0 * src[d];
            a = fmaf(v1, src[D_ + d], a);
            a = fmaf(v2, src[2*D_ + d], a);
            a = fmaf(v3, src[3*D_ + d], a);
            a = fmaf(v4, src[4*D_ + d], a);
            beff_s[idx] = a;
        }
    }

    // ===== P2b: inv_tot, P/Q transpose, zero h0 =====
    {
        for (int k = tid; k < 32; k += BLOCK) {
            int idx = bid*32 + k;
            int b = idx >> 7;
            int n = idx & 127;
            float s = 0.0f;
            for (int t = 0; t < T_; t++) s += mask[(b*T_ + t)*N_ + n];
            g_invtot[idx] = 1.0f / (s + 1.0f);
        }
        for (int idx = bid*BLOCK + tid; idx < N_*N_; idx += GRID*BLOCK) {
            int j = idx >> 7, i = idx & 127;
            float a = adjI[i*N_ + j];
            g_P[idx] = a;
            g_Q[idx] = a * rarW[i*N_ + j];
        }
        for (int idx = bid*BLOCK + tid; idx < HSZ; idx += GRID*BLOCK)
            g_hbuf[idx] = 0.0f;
    }
    grid_barrier();

    // ========== time loop ==========
    for (int t = 0; t < T_; t++) {
        const float* hprev = g_hbuf + (t & 1) * HSZ;
        float*       hnext = g_hbuf + ((t + 1) & 1) * HSZ;

        // ---------------- Phase A ----------------
        {
            const int b = bid >> 2;
            const int q = bid & 3;
            float* feat = scr + A_FEAT;
            float* wT   = scr + A_WT;
            float* rsv  = scr + A_RSV;
            int*   list = (int*)(scr + A_LIST);
            int*   cnt  = (int*)(scr + A_CNT);

            if (tid < 128) {
                float m = mask[(b*T_ + t)*N_ + tid];
                rsv[tid] = 0.5f * tanhfast(avg[(b*T_ + t)*N_ + tid] * g_invtot[b*N_ + tid]);
                bool ob = (m != 0.0f);
                unsigned msk = __ballot_sync(0xffffffffu, ob);
                if (lane == 0) { cnt[warp] = __popc(msk); ((unsigned*)cnt)[4 + warp] = msk; }
            }
            __syncthreads();
            const int nobs = cnt[0] + cnt[1] + cnt[2] + cnt[3];
            if (tid < 128) {
                unsigned msk = ((unsigned*)cnt)[4 + warp];
                if ((msk >> lane) & 1u) {
                    int off = __popc(msk & ((1u << lane) - 1u));
                    for (int ww = 0; ww < warp; ww++) off += cnt[ww];
                    list[off] = tid;
                }
            }
            __syncthreads();

            const int lo  = (nobs * q) >> 2;
            const int hi  = (nobs * (q + 1)) >> 2;
            const int myn = hi - lo;

            // stage feat: x at 0..63, rs at 64, pads 65..67, h at 68..131
            for (int idx = tid; idx < nobs*16; idx += BLOCK) {
                int jc = idx >> 4, qq = idx & 15;
                int j = list[jc];
                *(float4*)(feat + jc*KR + qq*4) =
                    *(const float4*)(obs + (size_t)((b*T_ + t)*N_ + j)*D_ + qq*4);
            }
            for (int idx = tid; idx < nobs*16; idx += BLOCK) {
                int jc = idx >> 4, qq = idx & 15;
                int j = list[jc];
                *(float4*)(feat + jc*KR + 68 + qq*4) =
                    *(const float4*)(hprev + (size_t)(b*N_ + j)*D_ + qq*4);
            }
            if (tid < nobs) {
                float* fr = feat + tid*KR;
                fr[64] = rsv[list[tid]];
                fr[65] = 0.0f; fr[66] = 0.0f; fr[67] = 0.0f;
            }
            // stage wT[jc][ic] (lane = ic, conflict-free)
            {
                int jc0 = warp;
                int ic  = lane;
                int i   = (ic < myn) ? list[lo + ic] : 0;
                float rsi = rsv[i];
                bool valid = (ic < myn);
                for (int jc = jc0; jc < nobs; jc += 32) {
                    int j = list[jc];
                    float wv = 0.0f;
                    if (valid) {
                        if (j == i) wv = 1.0f;
                        else wv = g_P[j*N_ + i] - g_Q[j*N_ + i] * fabsf(rsi - rsv[j]);
                    }
                    wT[jc*32 + ic] = wv;
                }
            }
            __syncthreads();

            // GEMM: 2-row x 1-col tiles
            const int RG2 = (myn + 1) >> 1;
            for (int tt = tid; tt < RG2*129; tt += BLOCK) {
                int rg = tt / 129;
                int cc = tt - rg*129;
                int c  = (cc < 65) ? cc : (cc + 3);
                const float* wp = wT + rg*2;
                const float* fp = feat + c;
                float ax = 0.0f, ay = 0.0f;
                #pragma unroll 4
                for (int jc = 0; jc < nobs; jc++) {
                    float fv = fp[jc*KR];
                    float2 w2 = *(const float2*)(wp + jc*32);
                    ax = fmaf(w2.x, fv, ax);
                    ay = fmaf(w2.y, fv, ay);
                }
                int ic0 = rg*2;
                {
                    int i = list[lo + ic0];
                    g_comb[(size_t)(b*N_ + i)*KR + c] = ax;
                }
                if (ic0 + 1 < myn) {
                    int i = list[lo + ic0 + 1];
                    g_comb[(size_t)(b*N_ + i)*KR + c] = ay;
                }
            }
        }
        grid_barrier();

        // ---------------- Phase B ----------------
        {
            const int n = n_node;
            float* combs = scr + B_COMB;
            float* zcs   = scr + B_ZCS;
            float* hs    = scr + B_HS;
            float* us    = scr + B_US;
            float* cxs   = scr + B_CX;
            float* ms    = scr + B_MS;
            int*   listB = (int*)(scr + B_LISTB);
            int*   lenS  = (int*)(scr + B_LEN);
            int*   pnB   = (int*)(scr + B_PNB);

            if (tid < 32) {
                int b = tid;
                float m = mask[(b*T_ + t)*N_ + n];
                ms[b] = m;
                float* zr = zcs + b*KR;
                zr[64] = 0.5f * tanhfast(avg[(b*T_ + t)*N_ + n] * g_invtot[b*N_ + n]);
                zr[65] = 0.0f; zr[66] = 0.0f; zr[67] = 0.0f;
                lenS[b] = lengths[b];
                bool ob = (m != 0.0f);
                unsigned msk = __ballot_sync(0xffffffffu, ob);
                if (ob) listB[__popc(msk & ((1u << tid) - 1u))] = b;
                if (tid == 0) *pnB = __popc(msk);
            }
            for (int idx = tid; idx < (B_*D_)/4; idx += BLOCK) {
                int b = idx >> 4, qq = idx & 15;
                *(float4*)(hs + b*64 + qq*4) =
                    *(const float4*)(hprev + (size_t)(b*N_ + n)*D_ + qq*4);
            }
            __syncthreads();
            const int nB = *pnB;
            const int BP = (nB + 1) >> 1;

            for (int idx = tid; idx < nB*33; idx += BLOCK) {
                int bc = idx / 33;
                int qq = idx - bc*33;
                int b  = listB[bc];
                *(float4*)(combs + b*KR + qq*4) =
                    *(const float4*)(g_comb + (size_t)(b*N_ + n)*KR + qq*4);
            }
            for (int idx = tid; idx < nB*16; idx += BLOCK) {
                int bc = idx >> 4, qq = idx & 15;
                int b  = listB[bc];
                *(float4*)(zcs + b*KR + qq*4) =
                    *(const float4*)(obs + (size_t)((b*T_ + t)*N_ + n)*D_ + qq*4);
            }
            __syncthreads();

            // ---- pass1: warp-task = (gate r/u/cx, batch-pair), tile 2b x 2d ----
            const int d0 = lane*2;
            for (int tau = warp; tau < 3*BP; tau += 32) {
                int g  = tau % 3;              // 0=r, 1=u, 2=candx
                int bp = tau / 3;
                int b0 = listB[2*bp];
                int b1 = listB[min(2*bp + 1, nB - 1)];
                const float* W = Wst + g*KD132 + d0;
                // r/u read the aggregated comb; candidate-x reads raw [x|rs]
                const float* c0p = (g == 2) ? (zcs + b0*KR) : (combs + b0*KR);
                const float* c1p = (g == 2) ? (zcs + b1*KR) : (combs + b1*KR);
                float2 bias = *(const float2*)(beff_s + g*64 + d0);
                float2 a0 = bias, a1 = bias;
                int kend = (g == 2) ? 65 : KR;
                #pragma unroll 4
                for (int k = 0; k < kend; k++) {
                    float c0 = c0p[k], c1 = c1p[k];
                    float2 w = *(const float2*)(W + k*64);
                    a0.x = fmaf(c0, w.x, a0.x); a0.y = fmaf(c0, w.y, a0.y);
                    a1.x = fmaf(c1, w.x, a1.x); a1.y = fmaf(c1, w.y, a1.y);
                }
                if (g == 0) {
                    float2 h0v = *(const float2*)(hs + b0*64 + d0);
                    float2 h1v = *(const float2*)(hs + b1*64 + d0);
                    *(float2*)(zcs + b0*KR + 68 + d0) =
                        make_float2(sigfast(a0.x)*h0v.x, sigfast(a0.y)*h0v.y);
                    *(float2*)(zcs + b1*KR + 68 + d0) =
                        make_float2(sigfast(a1.x)*h1v.x, sigfast(a1.y)*h1v.y);
                } else if (g == 1) {
                    *(float2*)(us + b0*64 + d0) = make_float2(sigfast(a0.x), sigfast(a0.y));
                    *(float2*)(us + b1*64 + d0) = make_float2(sigfast(a1.x), sigfast(a1.y));
                } else {
                    *(float2*)(cxs + b0*64 + d0) = a0;
                    *(float2*)(cxs + b1*64 + d0) = a1;
                }
            }
            __syncthreads();

            // ---- pass2: candh on warps < BP; carry on the rest ----
            if (warp < BP) {
                int bp = warp;
                int b0 = listB[2*bp];
                int b1 = listB[min(2*bp + 1, nB - 1)];
                const float* W   = Wst + 2*KD132 + 68*64 + d0;
                const float* z0p = zcs + b0*KR + 68;
                const float* z1p = zcs + b1*KR + 68;
                float2 a0 = *(const float2*)(cxs + b0*64 + d0);
                float2 a1 = *(const float2*)(cxs + b1*64 + d0);
                #pragma unroll 4
                for (int k = 0; k < 64; k++) {
                    float c0 = z0p[k], c1 = z1p[k];
                    float2 w = *(const float2*)(W + k*64);
                    a0.x = fmaf(c0, w.x, a0.x); a0.y = fmaf(c0, w.y, a0.y);
                    a1.x = fmaf(c1, w.x, a1.x); a1.y = fmaf(c1, w.y, a1.y);
                }
                float2 h10 = *(const float2*)(z0p + d0);
                float2 h11 = *(const float2*)(z1p + d0);
                float2 u0  = *(const float2*)(us + b0*64 + d0);
                float2 u1  = *(const float2*)(us + b1*64 + d0);
                float2 v0 = make_float2(h10.x + u0.x*(tanhfast(a0.x) - h10.x),
                                        h10.y + u0.y*(tanhfast(a0.y) - h10.y));
                float2 v1 = make_float2(h11.x + u1.x*(tanhfast(a1.x) - h11.x),
                                        h11.y + u1.y*(tanhfast(a1.y) - h11.y));
                *(float2*)(hnext + (size_t)(b0*N_ + n)*D_ + d0) = v0;
                *(float2*)(hnext + (size_t)(b1*N_ + n)*D_ + d0) = v1;
                if (t == lenS[b0] - 1) *(float2*)(out + (size_t)(b0*N_ + n)*D_ + d0) = v0;
                if (t == lenS[b1] - 1) *(float2*)(out + (size_t)(b1*N_ + n)*D_ + d0) = v1;
            } else {
                int nw = 32 - BP;
                for (int idx = (warp - BP)*32 + lane; idx < B_*D_; idx += nw*32) {
                    int b = idx >> 6, d = idx & 63;
                    if (ms[b] == 0.0f) {
                        float v = hs[idx];
                        hnext[(size_t)(b*N_ + n)*D_ + d] = v;
                        if (t == lenS[b] - 1) out[(size_t)(b*N_ + n)*D_ + d] = v;
                    }
                }
            }
        }
        grid_barrier();
    }
}

extern "C" void kernel_launch(void* const* d_in, const int* in_sizes, int n_in,
                              void* d_out, int out_size) {
    const float* obs     = (const float*)d_in[0];
    const float* mask    = (const float*)d_in[2];
    const int*   lengths = (const int*)d_in[5];
    const float* avg     = (const float*)d_in[6];
    const float* vpe     = (const float*)d_in[7];
    const float* rarW    = (const float*)d_in[8];
    const float* adjI    = (const float*)d_in[9];
    const float* W1      = (const float*)d_in[10];
    const float* b1      = (const float*)d_in[11];
    const float* W2      = (const float*)d_in[12];
    const float* b2      = (const float*)d_in[13];
    const float* Wu      = (const float*)d_in[14];
    const float* bu      = (const float*)d_in[15];
    const float* Wr      = (const float*)d_in[16];
    const float* br      = (const float*)d_in[17];
    const float* Wc      = (const float*)d_in[18];
    const float* bc      = (const float*)d_in[19];
    float* out = (float*)d_out;

    cudaFuncSetAttribute(cgrnn_persistent,
                         cudaFuncAttributeMaxDynamicSharedMemorySize, SMEM_BYTES);
    cgrnn_persistent<<<GRID, BLOCK, SMEM_BYTES>>>(
        obs, mask, lengths, avg, vpe, rarW, adjI,
        W1, b1, W2, b2, Wr, br, Wu, bu, Wc, bc, out);
}